// round 2
// baseline (speedup 1.0000x reference)
#include <cuda_runtime.h>
#include <math.h>

#define DMODEL 1024
#define NHEAD  16
#define HD     64
#define BATCH  4
#define SEQ    2048
#define MROWS  (BATCH*SEQ)   // 8192

// Scratch (allocation-free rule: __device__ globals)
__device__ float g_h[MROWS*DMODEL];
__device__ float g_q[MROWS*DMODEL];
__device__ float g_k[MROWS*DMODEL];
__device__ float g_v[MROWS*DMODEL];
__device__ float g_attn[MROWS*DMODEL];

// ---------------- LayerNorm: one block per row ----------------
__global__ void ln_kernel(const float* __restrict__ x,
                          const float* __restrict__ gamma,
                          const float* __restrict__ beta,
                          float* __restrict__ out) {
    int row = blockIdx.x;
    const float* xr = x + (size_t)row * DMODEL;
    float* orow = out + (size_t)row * DMODEL;
    int t = threadIdx.x;                       // 256 threads, 4 floats each
    float4 xv = reinterpret_cast<const float4*>(xr)[t];
    float s  = xv.x + xv.y + xv.z + xv.w;
    float s2 = xv.x*xv.x + xv.y*xv.y + xv.z*xv.z + xv.w*xv.w;
    int lane = t & 31, warp = t >> 5;
    #pragma unroll
    for (int o = 16; o; o >>= 1) {
        s  += __shfl_xor_sync(0xffffffffu, s,  o);
        s2 += __shfl_xor_sync(0xffffffffu, s2, o);
    }
    __shared__ float sh[16];
    if (lane == 0) { sh[warp] = s; sh[8 + warp] = s2; }
    __syncthreads();
    if (t == 0) {
        float a = 0.f, b = 0.f;
        #pragma unroll
        for (int i = 0; i < 8; i++) { a += sh[i]; b += sh[8 + i]; }
        sh[0] = a; sh[1] = b;
    }
    __syncthreads();
    float mean = sh[0] * (1.0f / DMODEL);
    float var  = sh[1] * (1.0f / DMODEL) - mean * mean;
    float rstd = rsqrtf(var + 1e-5f);
    float4 gv = reinterpret_cast<const float4*>(gamma)[t];
    float4 bv = reinterpret_cast<const float4*>(beta)[t];
    float4 ov;
    ov.x = (xv.x - mean) * rstd * gv.x + bv.x;
    ov.y = (xv.y - mean) * rstd * gv.y + bv.y;
    ov.z = (xv.z - mean) * rstd * gv.z + bv.z;
    ov.w = (xv.w - mean) * rstd * gv.w + bv.w;
    reinterpret_cast<float4*>(orow)[t] = ov;
}

// ------------- SGEMM 128x128x16, 256 thr, 8x8 microtile: C = A@W + bias -------------
__global__ __launch_bounds__(256, 1)
void gemm_bias_kernel(const float* __restrict__ A, const float* __restrict__ W,
                      const float* __restrict__ bias, float* __restrict__ C) {
    __shared__ float As[16][128];   // [k][m] (A transposed in smem)
    __shared__ float Ws[16][128];   // [k][n]
    int tid = threadIdx.x;
    int bm = blockIdx.y * 128;
    int bn = blockIdx.x * 128;
    int tx = tid & 15, ty = tid >> 4;
    int m0 = ty * 8, n0 = tx * 8;
    float acc[8][8];
    #pragma unroll
    for (int i = 0; i < 8; i++)
        #pragma unroll
        for (int j = 0; j < 8; j++) acc[i][j] = 0.f;

    for (int k0 = 0; k0 < DMODEL; k0 += 16) {
        #pragma unroll
        for (int l = 0; l < 2; l++) {
            int f  = tid * 2 + l;               // 512 float4s of A tile
            int r  = f >> 2;
            int c4 = (f & 3) * 4;
            float4 av = *reinterpret_cast<const float4*>(
                A + (size_t)(bm + r) * DMODEL + k0 + c4);
            As[c4 + 0][r] = av.x; As[c4 + 1][r] = av.y;
            As[c4 + 2][r] = av.z; As[c4 + 3][r] = av.w;
            int wr = f >> 5;
            int wc = (f & 31) * 4;
            *reinterpret_cast<float4*>(&Ws[wr][wc]) =
                *reinterpret_cast<const float4*>(W + (size_t)(k0 + wr) * DMODEL + bn + wc);
        }
        __syncthreads();
        #pragma unroll
        for (int kk = 0; kk < 16; kk++) {
            float a[8], w[8];
            *reinterpret_cast<float4*>(&a[0]) = *reinterpret_cast<float4*>(&As[kk][m0]);
            *reinterpret_cast<float4*>(&a[4]) = *reinterpret_cast<float4*>(&As[kk][m0 + 4]);
            *reinterpret_cast<float4*>(&w[0]) = *reinterpret_cast<float4*>(&Ws[kk][n0]);
            *reinterpret_cast<float4*>(&w[4]) = *reinterpret_cast<float4*>(&Ws[kk][n0 + 4]);
            #pragma unroll
            for (int i = 0; i < 8; i++)
                #pragma unroll
                for (int j = 0; j < 8; j++) acc[i][j] += a[i] * w[j];
        }
        __syncthreads();
    }
    #pragma unroll
    for (int i = 0; i < 8; i++) {
        #pragma unroll
        for (int j = 0; j < 8; j++) {
            C[(size_t)(bm + m0 + i) * DMODEL + bn + n0 + j] = acc[i][j] + bias[bn + n0 + j];
        }
    }
}

// ------------- Causal flash attention, fp32, 64x64 tiles, 4x4 microtile -------------
// grid: (S/64, NHEAD, BATCH), 256 threads
__global__ __launch_bounds__(256, 1)
void attn_kernel(const float* __restrict__ Q, const float* __restrict__ K,
                 const float* __restrict__ V, float* __restrict__ O) {
    extern __shared__ float sm[];
    float* Qs = sm;                 // [d][m]  64 x 68
    float* Ks = Qs + 64 * 68;       // [d][n]
    float* Vs = Ks + 64 * 68;       // [n][d]
    float* Ps = Vs + 64 * 68;       // [n][m]
    const int qt = blockIdx.x, h = blockIdx.y, b = blockIdx.z;
    const int tid = threadIdx.x;
    const int tx = tid & 15, ty = tid >> 4;
    const int m0 = ty * 4, n0 = tx * 4, d0 = tx * 4;
    const size_t base = (size_t)b * SEQ * DMODEL + (size_t)h * HD;

    // load Q tile (transposed into smem)
    #pragma unroll
    for (int i = 0; i < 4; i++) {
        int idx = tid + i * 256;
        int r = idx >> 4, c4 = (idx & 15) * 4;
        float4 qv = *reinterpret_cast<const float4*>(
            Q + base + (size_t)(qt * 64 + r) * DMODEL + c4);
        Qs[(c4 + 0) * 68 + r] = qv.x; Qs[(c4 + 1) * 68 + r] = qv.y;
        Qs[(c4 + 2) * 68 + r] = qv.z; Qs[(c4 + 3) * 68 + r] = qv.w;
    }

    float mstate[4], lstate[4], oacc[4][4];
    #pragma unroll
    for (int i = 0; i < 4; i++) {
        mstate[i] = -1e30f; lstate[i] = 0.f;
        #pragma unroll
        for (int j = 0; j < 4; j++) oacc[i][j] = 0.f;
    }

    for (int j = 0; j <= qt; j++) {
        __syncthreads();
        #pragma unroll
        for (int i = 0; i < 4; i++) {
            int idx = tid + i * 256;
            int r = idx >> 4, c4 = (idx & 15) * 4;
            float4 kv = *reinterpret_cast<const float4*>(
                K + base + (size_t)(j * 64 + r) * DMODEL + c4);
            Ks[(c4 + 0) * 68 + r] = kv.x; Ks[(c4 + 1) * 68 + r] = kv.y;
            Ks[(c4 + 2) * 68 + r] = kv.z; Ks[(c4 + 3) * 68 + r] = kv.w;
            float4 vv = *reinterpret_cast<const float4*>(
                V + base + (size_t)(j * 64 + r) * DMODEL + c4);
            *reinterpret_cast<float4*>(&Vs[r * 68 + c4]) = vv;
        }
        __syncthreads();

        // S = Q K^T (64x64x64)
        float sacc[4][4];
        #pragma unroll
        for (int mi = 0; mi < 4; mi++)
            #pragma unroll
            for (int ni = 0; ni < 4; ni++) sacc[mi][ni] = 0.f;
        #pragma unroll 8
        for (int d = 0; d < 64; d++) {
            float av[4], bv[4];
            *reinterpret_cast<float4*>(av) = *reinterpret_cast<float4*>(&Qs[d * 68 + m0]);
            *reinterpret_cast<float4*>(bv) = *reinterpret_cast<float4*>(&Ks[d * 68 + n0]);
            #pragma unroll
            for (int mi = 0; mi < 4; mi++)
                #pragma unroll
                for (int ni = 0; ni < 4; ni++) sacc[mi][ni] += av[mi] * bv[ni];
        }

        // online softmax (row groups = 16 lanes sharing ty)
        const float scale = 0.125f;  // 1/sqrt(64)
        int qg0 = qt * 64 + m0, kg0 = j * 64 + n0;
        #pragma unroll
        for (int mi = 0; mi < 4; mi++) {
            float rmax = -1e30f;
            #pragma unroll
            for (int ni = 0; ni < 4; ni++) {
                float s = sacc[mi][ni] * scale;
                if (kg0 + ni > qg0 + mi) s = -1e30f;
                sacc[mi][ni] = s;
                rmax = fmaxf(rmax, s);
            }
            #pragma unroll
            for (int o = 8; o; o >>= 1)
                rmax = fmaxf(rmax, __shfl_xor_sync(0xffffffffu, rmax, o));
            float mnew  = fmaxf(mstate[mi], rmax);
            float alpha = __expf(mstate[mi] - mnew);
            mstate[mi]  = mnew;
            float rsum = 0.f;
            #pragma unroll
            for (int ni = 0; ni < 4; ni++) {
                float p = __expf(sacc[mi][ni] - mnew);
                sacc[mi][ni] = p;
                rsum += p;
            }
            #pragma unroll
            for (int o = 8; o; o >>= 1)
                rsum += __shfl_xor_sync(0xffffffffu, rsum, o);
            lstate[mi] = lstate[mi] * alpha + rsum;
            #pragma unroll
            for (int di = 0; di < 4; di++) oacc[mi][di] *= alpha;
        }

        // P -> smem (transposed [n][m])
        #pragma unroll
        for (int ni = 0; ni < 4; ni++) {
            float4 pv = make_float4(sacc[0][ni], sacc[1][ni], sacc[2][ni], sacc[3][ni]);
            *reinterpret_cast<float4*>(&Ps[(n0 + ni) * 68 + m0]) = pv;
        }
        __syncthreads();

        // O += P @ V
        #pragma unroll 8
        for (int n = 0; n < 64; n++) {
            float pv[4], vv[4];
            *reinterpret_cast<float4*>(pv) = *reinterpret_cast<float4*>(&Ps[n * 68 + m0]);
            *reinterpret_cast<float4*>(vv) = *reinterpret_cast<float4*>(&Vs[n * 68 + d0]);
            #pragma unroll
            for (int mi = 0; mi < 4; mi++)
                #pragma unroll
                for (int di = 0; di < 4; di++) oacc[mi][di] += pv[mi] * vv[di];
        }
    }

    #pragma unroll
    for (int mi = 0; mi < 4; mi++) {
        float inv = 1.0f / lstate[mi];
        #pragma unroll
        for (int di = 0; di < 4; di++)
            O[base + (size_t)(qt * 64 + m0 + mi) * DMODEL + d0 + di] = oacc[mi][di] * inv;
    }
}

extern "C" void kernel_launch(void* const* d_in, const int* in_sizes, int n_in,
                              void* d_out, int out_size) {
    (void)in_sizes; (void)n_in; (void)out_size;
    const float* x     = (const float*)d_in[0];
    const float* Wq    = (const float*)d_in[1];
    const float* bq    = (const float*)d_in[2];
    const float* Wk    = (const float*)d_in[3];
    const float* bk    = (const float*)d_in[4];
    const float* Wv    = (const float*)d_in[5];
    const float* bv    = (const float*)d_in[6];
    const float* Wo    = (const float*)d_in[7];
    const float* bo    = (const float*)d_in[8];
    const float* gamma = (const float*)d_in[9];
    const float* beta  = (const float*)d_in[10];
    float* out = (float*)d_out;

    float *h, *q, *k, *v, *attn;
    cudaGetSymbolAddress((void**)&h,    g_h);
    cudaGetSymbolAddress((void**)&q,    g_q);
    cudaGetSymbolAddress((void**)&k,    g_k);
    cudaGetSymbolAddress((void**)&v,    g_v);
    cudaGetSymbolAddress((void**)&attn, g_attn);

    ln_kernel<<<MROWS, 256>>>(x, gamma, beta, h);

    dim3 ggrid(DMODEL / 128, MROWS / 128);   // (8, 64)
    gemm_bias_kernel<<<ggrid, 256>>>(h, Wq, bq, q);
    gemm_bias_kernel<<<ggrid, 256>>>(h, Wk, bk, k);
    gemm_bias_kernel<<<ggrid, 256>>>(h, Wv, bv, v);

    int smem = 4 * 64 * 68 * (int)sizeof(float);   // 69632 B
    cudaFuncSetAttribute(attn_kernel, cudaFuncAttributeMaxDynamicSharedMemorySize, smem);
    attn_kernel<<<dim3(SEQ / 64, NHEAD, BATCH), 256, smem>>>(q, k, v, attn);

    gemm_bias_kernel<<<ggrid, 256>>>(attn, Wo, bo, out);
}

// round 3
// speedup vs baseline: 1.6482x; 1.6482x over previous
#include <cuda_runtime.h>
#include <math.h>

#define DMODEL 1024
#define NHEAD  16
#define HD     64
#define BATCH  4
#define SEQ    2048
#define MROWS  (BATCH*SEQ)   // 8192

// Scratch (allocation-free rule: __device__ globals)
__device__ float g_h[MROWS*DMODEL];
__device__ float g_q[MROWS*DMODEL];
__device__ float g_k[MROWS*DMODEL];
__device__ float g_v[MROWS*DMODEL];
__device__ float g_attn[MROWS*DMODEL];

__device__ __forceinline__ float to_tf32(float x) {
    float r;
    asm("cvt.rna.tf32.f32 %0, %1;" : "=f"(r) : "f"(x));
    return r;
}

// ---------------- LayerNorm: one block per row ----------------
__global__ void ln_kernel(const float* __restrict__ x,
                          const float* __restrict__ gamma,
                          const float* __restrict__ beta,
                          float* __restrict__ out) {
    int row = blockIdx.x;
    const float* xr = x + (size_t)row * DMODEL;
    float* orow = out + (size_t)row * DMODEL;
    int t = threadIdx.x;                       // 256 threads, 4 floats each
    float4 xv = reinterpret_cast<const float4*>(xr)[t];
    float s  = xv.x + xv.y + xv.z + xv.w;
    float s2 = xv.x*xv.x + xv.y*xv.y + xv.z*xv.z + xv.w*xv.w;
    int lane = t & 31, warp = t >> 5;
    #pragma unroll
    for (int o = 16; o; o >>= 1) {
        s  += __shfl_xor_sync(0xffffffffu, s,  o);
        s2 += __shfl_xor_sync(0xffffffffu, s2, o);
    }
    __shared__ float sh[16];
    if (lane == 0) { sh[warp] = s; sh[8 + warp] = s2; }
    __syncthreads();
    if (t == 0) {
        float a = 0.f, b = 0.f;
        #pragma unroll
        for (int i = 0; i < 8; i++) { a += sh[i]; b += sh[8 + i]; }
        sh[0] = a; sh[1] = b;
    }
    __syncthreads();
    float mean = sh[0] * (1.0f / DMODEL);
    float var  = sh[1] * (1.0f / DMODEL) - mean * mean;
    float rstd = rsqrtf(var + 1e-5f);
    float4 gv = reinterpret_cast<const float4*>(gamma)[t];
    float4 bv = reinterpret_cast<const float4*>(beta)[t];
    float4 ov;
    ov.x = (xv.x - mean) * rstd * gv.x + bv.x;
    ov.y = (xv.y - mean) * rstd * gv.y + bv.y;
    ov.z = (xv.z - mean) * rstd * gv.z + bv.z;
    ov.w = (xv.w - mean) * rstd * gv.w + bv.w;
    reinterpret_cast<float4*>(orow)[t] = ov;
}

// ------------- tf32 tensor-core GEMM 128x128x32: C = A@W + bias -------------
// 256 threads = 8 warps, warp tile 64x32 (mma.m16n8k8: 4 m-frags x 4 n-frags x 4 k-steps)
// Smem: [k][m] / [k][n], stride 136 (== 8 mod 32) + XOR swizzle on bits[2:4]
// -> conflict-free STS and fragment LDS (verified bank maps).
__global__ __launch_bounds__(256, 2)
void gemm_bias_kernel(const float* __restrict__ A, const float* __restrict__ W,
                      const float* __restrict__ bias, float* __restrict__ C) {
    __shared__ float As[32 * 136];
    __shared__ float Ws[32 * 136];
    const int tid = threadIdx.x;
    const int bm = blockIdx.y * 128;
    const int bn = blockIdx.x * 128;
    const int lane = tid & 31;
    const int wid  = tid >> 5;
    const int warp_m = wid & 1;      // 2 warps along M
    const int warp_n = wid >> 1;     // 4 warps along N
    const int qid = lane >> 2;       // 0..7
    const int tg  = lane & 3;        // 0..3

    float acc[4][4][4];
    #pragma unroll
    for (int mi = 0; mi < 4; mi++)
        #pragma unroll
        for (int nj = 0; nj < 4; nj++)
            #pragma unroll
            for (int r = 0; r < 4; r++) acc[mi][nj][r] = 0.f;

    for (int k0 = 0; k0 < DMODEL; k0 += 32) {
        // Load A tile [128 x 32] -> As[k][m^swz]
        #pragma unroll
        for (int l = 0; l < 4; l++) {
            int f  = tid + l * 256;          // 0..1023
            int m  = f >> 3;                 // 0..127
            int kq = f & 7;                  // k/4 block (k>>2 for all 4 elems)
            float4 av = *reinterpret_cast<const float4*>(
                A + (size_t)(bm + m) * DMODEL + k0 + kq * 4);
            int ms = m ^ (kq << 2);
            As[(kq * 4 + 0) * 136 + ms] = to_tf32(av.x);
            As[(kq * 4 + 1) * 136 + ms] = to_tf32(av.y);
            As[(kq * 4 + 2) * 136 + ms] = to_tf32(av.z);
            As[(kq * 4 + 3) * 136 + ms] = to_tf32(av.w);
        }
        // Load W tile [32 x 128] -> Ws[k][n^swz] (vectorized: swizzle const per thread)
        #pragma unroll
        for (int l = 0; l < 4; l++) {
            int f  = tid + l * 256;
            int k  = f >> 5;                 // 0..31
            int n4 = (f & 31) * 4;
            float4 wv = *reinterpret_cast<const float4*>(
                W + (size_t)(k0 + k) * DMODEL + bn + n4);
            int c = ((k >> 2) & 7) << 2;
            float4 sv;
            sv.x = to_tf32(wv.x); sv.y = to_tf32(wv.y);
            sv.z = to_tf32(wv.z); sv.w = to_tf32(wv.w);
            *reinterpret_cast<float4*>(&Ws[k * 136 + (n4 ^ c)]) = sv;
        }
        __syncthreads();

        #pragma unroll
        for (int kk = 0; kk < 4; kk++) {
            const int kA0 = kk * 8 + tg;
            const int kA1 = kA0 + 4;
            const int c0 = ((kA0 >> 2) & 7) << 2;
            const int c1 = ((kA1 >> 2) & 7) << 2;
            unsigned a[4][4], b[4][2];
            #pragma unroll
            for (int mi = 0; mi < 4; mi++) {
                int mrow = warp_m * 64 + mi * 16 + qid;
                a[mi][0] = __float_as_uint(As[kA0 * 136 + (mrow ^ c0)]);
                a[mi][1] = __float_as_uint(As[kA0 * 136 + ((mrow + 8) ^ c0)]);
                a[mi][2] = __float_as_uint(As[kA1 * 136 + (mrow ^ c1)]);
                a[mi][3] = __float_as_uint(As[kA1 * 136 + ((mrow + 8) ^ c1)]);
            }
            #pragma unroll
            for (int nj = 0; nj < 4; nj++) {
                int ncol = warp_n * 32 + nj * 8 + qid;
                b[nj][0] = __float_as_uint(Ws[kA0 * 136 + (ncol ^ c0)]);
                b[nj][1] = __float_as_uint(Ws[kA1 * 136 + (ncol ^ c1)]);
            }
            #pragma unroll
            for (int mi = 0; mi < 4; mi++)
                #pragma unroll
                for (int nj = 0; nj < 4; nj++) {
                    asm volatile(
                        "mma.sync.aligned.m16n8k8.row.col.f32.tf32.tf32.f32 "
                        "{%0,%1,%2,%3}, {%4,%5,%6,%7}, {%8,%9}, {%0,%1,%2,%3};"
                        : "+f"(acc[mi][nj][0]), "+f"(acc[mi][nj][1]),
                          "+f"(acc[mi][nj][2]), "+f"(acc[mi][nj][3])
                        : "r"(a[mi][0]), "r"(a[mi][1]), "r"(a[mi][2]), "r"(a[mi][3]),
                          "r"(b[nj][0]), "r"(b[nj][1]));
                }
        }
        __syncthreads();
    }

    // Epilogue: c0:(row,col) c1:(row,col+1) c2:(row+8,col) c3:(row+8,col+1)
    #pragma unroll
    for (int mi = 0; mi < 4; mi++) {
        int row = bm + warp_m * 64 + mi * 16 + qid;
        #pragma unroll
        for (int nj = 0; nj < 4; nj++) {
            int col = bn + warp_n * 32 + nj * 8 + tg * 2;
            float b0 = bias[col], b1 = bias[col + 1];
            float2 v0 = make_float2(acc[mi][nj][0] + b0, acc[mi][nj][1] + b1);
            float2 v1 = make_float2(acc[mi][nj][2] + b0, acc[mi][nj][3] + b1);
            *reinterpret_cast<float2*>(&C[(size_t)row * DMODEL + col]) = v0;
            *reinterpret_cast<float2*>(&C[(size_t)(row + 8) * DMODEL + col]) = v1;
        }
    }
}

// ------------- Causal flash attention, fp32, 64x64 tiles, 4x4 microtile -------------
// grid: (S/64, NHEAD, BATCH), 256 threads
__global__ __launch_bounds__(256, 1)
void attn_kernel(const float* __restrict__ Q, const float* __restrict__ K,
                 const float* __restrict__ V, float* __restrict__ O) {
    extern __shared__ float sm[];
    float* Qs = sm;                 // [d][m]  64 x 68
    float* Ks = Qs + 64 * 68;       // [d][n]
    float* Vs = Ks + 64 * 68;       // [n][d]
    float* Ps = Vs + 64 * 68;       // [n][m]
    const int qt = blockIdx.x, h = blockIdx.y, b = blockIdx.z;
    const int tid = threadIdx.x;
    const int tx = tid & 15, ty = tid >> 4;
    const int m0 = ty * 4, n0 = tx * 4, d0 = tx * 4;
    const size_t base = (size_t)b * SEQ * DMODEL + (size_t)h * HD;

    // load Q tile (transposed into smem)
    #pragma unroll
    for (int i = 0; i < 4; i++) {
        int idx = tid + i * 256;
        int r = idx >> 4, c4 = (idx & 15) * 4;
        float4 qv = *reinterpret_cast<const float4*>(
            Q + base + (size_t)(qt * 64 + r) * DMODEL + c4);
        Qs[(c4 + 0) * 68 + r] = qv.x; Qs[(c4 + 1) * 68 + r] = qv.y;
        Qs[(c4 + 2) * 68 + r] = qv.z; Qs[(c4 + 3) * 68 + r] = qv.w;
    }

    float mstate[4], lstate[4], oacc[4][4];
    #pragma unroll
    for (int i = 0; i < 4; i++) {
        mstate[i] = -1e30f; lstate[i] = 0.f;
        #pragma unroll
        for (int j = 0; j < 4; j++) oacc[i][j] = 0.f;
    }

    for (int j = 0; j <= qt; j++) {
        __syncthreads();
        #pragma unroll
        for (int i = 0; i < 4; i++) {
            int idx = tid + i * 256;
            int r = idx >> 4, c4 = (idx & 15) * 4;
            float4 kv = *reinterpret_cast<const float4*>(
                K + base + (size_t)(j * 64 + r) * DMODEL + c4);
            Ks[(c4 + 0) * 68 + r] = kv.x; Ks[(c4 + 1) * 68 + r] = kv.y;
            Ks[(c4 + 2) * 68 + r] = kv.z; Ks[(c4 + 3) * 68 + r] = kv.w;
            float4 vv = *reinterpret_cast<const float4*>(
                V + base + (size_t)(j * 64 + r) * DMODEL + c4);
            *reinterpret_cast<float4*>(&Vs[r * 68 + c4]) = vv;
        }
        __syncthreads();

        // S = Q K^T (64x64x64)
        float sacc[4][4];
        #pragma unroll
        for (int mi = 0; mi < 4; mi++)
            #pragma unroll
            for (int ni = 0; ni < 4; ni++) sacc[mi][ni] = 0.f;
        #pragma unroll 8
        for (int d = 0; d < 64; d++) {
            float av[4], bv[4];
            *reinterpret_cast<float4*>(av) = *reinterpret_cast<float4*>(&Qs[d * 68 + m0]);
            *reinterpret_cast<float4*>(bv) = *reinterpret_cast<float4*>(&Ks[d * 68 + n0]);
            #pragma unroll
            for (int mi = 0; mi < 4; mi++)
                #pragma unroll
                for (int ni = 0; ni < 4; ni++) sacc[mi][ni] += av[mi] * bv[ni];
        }

        // online softmax (row groups = 16 lanes sharing ty)
        const float scale = 0.125f;  // 1/sqrt(64)
        int qg0 = qt * 64 + m0, kg0 = j * 64 + n0;
        #pragma unroll
        for (int mi = 0; mi < 4; mi++) {
            float rmax = -1e30f;
            #pragma unroll
            for (int ni = 0; ni < 4; ni++) {
                float s = sacc[mi][ni] * scale;
                if (kg0 + ni > qg0 + mi) s = -1e30f;
                sacc[mi][ni] = s;
                rmax = fmaxf(rmax, s);
            }
            #pragma unroll
            for (int o = 8; o; o >>= 1)
                rmax = fmaxf(rmax, __shfl_xor_sync(0xffffffffu, rmax, o));
            float mnew  = fmaxf(mstate[mi], rmax);
            float alpha = __expf(mstate[mi] - mnew);
            mstate[mi]  = mnew;
            float rsum = 0.f;
            #pragma unroll
            for (int ni = 0; ni < 4; ni++) {
                float p = __expf(sacc[mi][ni] - mnew);
                sacc[mi][ni] = p;
                rsum += p;
            }
            #pragma unroll
            for (int o = 8; o; o >>= 1)
                rsum += __shfl_xor_sync(0xffffffffu, rsum, o);
            lstate[mi] = lstate[mi] * alpha + rsum;
            #pragma unroll
            for (int di = 0; di < 4; di++) oacc[mi][di] *= alpha;
        }

        // P -> smem (transposed [n][m])
        #pragma unroll
        for (int ni = 0; ni < 4; ni++) {
            float4 pv = make_float4(sacc[0][ni], sacc[1][ni], sacc[2][ni], sacc[3][ni]);
            *reinterpret_cast<float4*>(&Ps[(n0 + ni) * 68 + m0]) = pv;
        }
        __syncthreads();

        // O += P @ V
        #pragma unroll 8
        for (int n = 0; n < 64; n++) {
            float pv[4], vv[4];
            *reinterpret_cast<float4*>(pv) = *reinterpret_cast<float4*>(&Ps[n * 68 + m0]);
            *reinterpret_cast<float4*>(vv) = *reinterpret_cast<float4*>(&Vs[n * 68 + d0]);
            #pragma unroll
            for (int mi = 0; mi < 4; mi++)
                #pragma unroll
                for (int di = 0; di < 4; di++) oacc[mi][di] += pv[mi] * vv[di];
        }
    }

    #pragma unroll
    for (int mi = 0; mi < 4; mi++) {
        float inv = 1.0f / lstate[mi];
        #pragma unroll
        for (int di = 0; di < 4; di++)
            O[base + (size_t)(qt * 64 + m0 + mi) * DMODEL + d0 + di] = oacc[mi][di] * inv;
    }
}

extern "C" void kernel_launch(void* const* d_in, const int* in_sizes, int n_in,
                              void* d_out, int out_size) {
    (void)in_sizes; (void)n_in; (void)out_size;
    const float* x     = (const float*)d_in[0];
    const float* Wq    = (const float*)d_in[1];
    const float* bq    = (const float*)d_in[2];
    const float* Wk    = (const float*)d_in[3];
    const float* bk    = (const float*)d_in[4];
    const float* Wv    = (const float*)d_in[5];
    const float* bv    = (const float*)d_in[6];
    const float* Wo    = (const float*)d_in[7];
    const float* bo    = (const float*)d_in[8];
    const float* gamma = (const float*)d_in[9];
    const float* beta  = (const float*)d_in[10];
    float* out = (float*)d_out;

    float *h, *q, *k, *v, *attn;
    cudaGetSymbolAddress((void**)&h,    g_h);
    cudaGetSymbolAddress((void**)&q,    g_q);
    cudaGetSymbolAddress((void**)&k,    g_k);
    cudaGetSymbolAddress((void**)&v,    g_v);
    cudaGetSymbolAddress((void**)&attn, g_attn);

    ln_kernel<<<MROWS, 256>>>(x, gamma, beta, h);

    dim3 ggrid(DMODEL / 128, MROWS / 128);   // (8, 64)
    gemm_bias_kernel<<<ggrid, 256>>>(h, Wq, bq, q);
    gemm_bias_kernel<<<ggrid, 256>>>(h, Wk, bk, k);
    gemm_bias_kernel<<<ggrid, 256>>>(h, Wv, bv, v);

    int smem = 4 * 64 * 68 * (int)sizeof(float);   // 69632 B
    cudaFuncSetAttribute(attn_kernel, cudaFuncAttributeMaxDynamicSharedMemorySize, smem);
    attn_kernel<<<dim3(SEQ / 64, NHEAD, BATCH), 256, smem>>>(q, k, v, attn);

    gemm_bias_kernel<<<ggrid, 256>>>(attn, Wo, bo, out);
}

// round 7
// speedup vs baseline: 2.9490x; 1.7892x over previous
#include <cuda_runtime.h>
#include <math.h>

#define DMODEL 1024
#define NHEAD  16
#define HD     64
#define BATCH  4
#define SEQ    2048
#define MROWS  (BATCH*SEQ)   // 8192

// Scratch (allocation-free rule: __device__ globals)
__device__ float g_h[MROWS*DMODEL];
__device__ float g_q[MROWS*DMODEL];
__device__ float g_k[MROWS*DMODEL];
__device__ float g_v[MROWS*DMODEL];
__device__ float g_attn[MROWS*DMODEL];

__device__ __forceinline__ float to_tf32(float x) {
    float r;
    asm("cvt.rna.tf32.f32 %0, %1;" : "=f"(r) : "f"(x));
    return r;
}

// ---------------- LayerNorm: one block per row ----------------
__global__ void ln_kernel(const float* __restrict__ x,
                          const float* __restrict__ gamma,
                          const float* __restrict__ beta,
                          float* __restrict__ out) {
    int row = blockIdx.x;
    const float* xr = x + (size_t)row * DMODEL;
    float* orow = out + (size_t)row * DMODEL;
    int t = threadIdx.x;                       // 256 threads, 4 floats each
    float4 xv = reinterpret_cast<const float4*>(xr)[t];
    float s  = xv.x + xv.y + xv.z + xv.w;
    float s2 = xv.x*xv.x + xv.y*xv.y + xv.z*xv.z + xv.w*xv.w;
    int lane = t & 31, warp = t >> 5;
    #pragma unroll
    for (int o = 16; o; o >>= 1) {
        s  += __shfl_xor_sync(0xffffffffu, s,  o);
        s2 += __shfl_xor_sync(0xffffffffu, s2, o);
    }
    __shared__ float sh[16];
    if (lane == 0) { sh[warp] = s; sh[8 + warp] = s2; }
    __syncthreads();
    if (t == 0) {
        float a = 0.f, b = 0.f;
        #pragma unroll
        for (int i = 0; i < 8; i++) { a += sh[i]; b += sh[8 + i]; }
        sh[0] = a; sh[1] = b;
    }
    __syncthreads();
    float mean = sh[0] * (1.0f / DMODEL);
    float var  = sh[1] * (1.0f / DMODEL) - mean * mean;
    float rstd = rsqrtf(var + 1e-5f);
    float4 gv = reinterpret_cast<const float4*>(gamma)[t];
    float4 bv = reinterpret_cast<const float4*>(beta)[t];
    float4 ov;
    ov.x = (xv.x - mean) * rstd * gv.x + bv.x;
    ov.y = (xv.y - mean) * rstd * gv.y + bv.y;
    ov.z = (xv.z - mean) * rstd * gv.z + bv.z;
    ov.w = (xv.w - mean) * rstd * gv.w + bv.w;
    reinterpret_cast<float4*>(orow)[t] = ov;
}

// ------------- tf32 tensor-core GEMM 128x128x32: C = A@W + bias -------------
__global__ __launch_bounds__(256, 2)
void gemm_bias_kernel(const float* __restrict__ A, const float* __restrict__ W,
                      const float* __restrict__ bias, float* __restrict__ C) {
    __shared__ float As[32 * 136];
    __shared__ float Ws[32 * 136];
    const int tid = threadIdx.x;
    const int bm = blockIdx.y * 128;
    const int bn = blockIdx.x * 128;
    const int lane = tid & 31;
    const int wid  = tid >> 5;
    const int warp_m = wid & 1;      // 2 warps along M
    const int warp_n = wid >> 1;     // 4 warps along N
    const int qid = lane >> 2;       // 0..7
    const int tg  = lane & 3;        // 0..3

    float acc[4][4][4];
    #pragma unroll
    for (int mi = 0; mi < 4; mi++)
        #pragma unroll
        for (int nj = 0; nj < 4; nj++)
            #pragma unroll
            for (int r = 0; r < 4; r++) acc[mi][nj][r] = 0.f;

    for (int k0 = 0; k0 < DMODEL; k0 += 32) {
        #pragma unroll
        for (int l = 0; l < 4; l++) {
            int f  = tid + l * 256;          // 0..1023
            int m  = f >> 3;                 // 0..127
            int kq = f & 7;                  // k/4 block
            float4 av = *reinterpret_cast<const float4*>(
                A + (size_t)(bm + m) * DMODEL + k0 + kq * 4);
            int ms = m ^ (kq << 2);
            As[(kq * 4 + 0) * 136 + ms] = to_tf32(av.x);
            As[(kq * 4 + 1) * 136 + ms] = to_tf32(av.y);
            As[(kq * 4 + 2) * 136 + ms] = to_tf32(av.z);
            As[(kq * 4 + 3) * 136 + ms] = to_tf32(av.w);
        }
        #pragma unroll
        for (int l = 0; l < 4; l++) {
            int f  = tid + l * 256;
            int k  = f >> 5;                 // 0..31
            int n4 = (f & 31) * 4;
            float4 wv = *reinterpret_cast<const float4*>(
                W + (size_t)(k0 + k) * DMODEL + bn + n4);
            int c = ((k >> 2) & 7) << 2;
            float4 sv;
            sv.x = to_tf32(wv.x); sv.y = to_tf32(wv.y);
            sv.z = to_tf32(wv.z); sv.w = to_tf32(wv.w);
            *reinterpret_cast<float4*>(&Ws[k * 136 + (n4 ^ c)]) = sv;
        }
        __syncthreads();

        #pragma unroll
        for (int kk = 0; kk < 4; kk++) {
            const int kA0 = kk * 8 + tg;
            const int kA1 = kA0 + 4;
            const int c0 = ((kA0 >> 2) & 7) << 2;
            const int c1 = ((kA1 >> 2) & 7) << 2;
            unsigned a[4][4], b[4][2];
            #pragma unroll
            for (int mi = 0; mi < 4; mi++) {
                int mrow = warp_m * 64 + mi * 16 + qid;
                a[mi][0] = __float_as_uint(As[kA0 * 136 + (mrow ^ c0)]);
                a[mi][1] = __float_as_uint(As[kA0 * 136 + ((mrow + 8) ^ c0)]);
                a[mi][2] = __float_as_uint(As[kA1 * 136 + (mrow ^ c1)]);
                a[mi][3] = __float_as_uint(As[kA1 * 136 + ((mrow + 8) ^ c1)]);
            }
            #pragma unroll
            for (int nj = 0; nj < 4; nj++) {
                int ncol = warp_n * 32 + nj * 8 + qid;
                b[nj][0] = __float_as_uint(Ws[kA0 * 136 + (ncol ^ c0)]);
                b[nj][1] = __float_as_uint(Ws[kA1 * 136 + (ncol ^ c1)]);
            }
            #pragma unroll
            for (int mi = 0; mi < 4; mi++)
                #pragma unroll
                for (int nj = 0; nj < 4; nj++) {
                    asm volatile(
                        "mma.sync.aligned.m16n8k8.row.col.f32.tf32.tf32.f32 "
                        "{%0,%1,%2,%3}, {%4,%5,%6,%7}, {%8,%9}, {%0,%1,%2,%3};"
                        : "+f"(acc[mi][nj][0]), "+f"(acc[mi][nj][1]),
                          "+f"(acc[mi][nj][2]), "+f"(acc[mi][nj][3])
                        : "r"(a[mi][0]), "r"(a[mi][1]), "r"(a[mi][2]), "r"(a[mi][3]),
                          "r"(b[nj][0]), "r"(b[nj][1]));
                }
        }
        __syncthreads();
    }

    #pragma unroll
    for (int mi = 0; mi < 4; mi++) {
        int row = bm + warp_m * 64 + mi * 16 + qid;
        #pragma unroll
        for (int nj = 0; nj < 4; nj++) {
            int col = bn + warp_n * 32 + nj * 8 + tg * 2;
            float b0 = bias[col], b1 = bias[col + 1];
            float2 v0 = make_float2(acc[mi][nj][0] + b0, acc[mi][nj][1] + b1);
            float2 v1 = make_float2(acc[mi][nj][2] + b0, acc[mi][nj][3] + b1);
            *reinterpret_cast<float2*>(&C[(size_t)row * DMODEL + col]) = v0;
            *reinterpret_cast<float2*>(&C[(size_t)(row + 8) * DMODEL + col]) = v1;
        }
    }
}

// ------------- tf32 tensor-core causal flash attention -------------
// CTA: 128 q-rows, 8 warps, each warp owns 16 rows x full 64-key width.
// grid: (SEQ/128, NHEAD, BATCH), 256 threads.
// Ks: blocked layout float[16][64][4] with XOR swizzle (transposed K: [d][key]).
// Vs: [key][hd] stride 72. Both verified conflict-free for STS.128 + B-frag LDS.
__global__ __launch_bounds__(256, 1)
void attn_tc_kernel(const float* __restrict__ Q, const float* __restrict__ K,
                    const float* __restrict__ V, float* __restrict__ O) {
    __shared__ float Ks[16 * 256];   // 16KB
    __shared__ float Vs[64 * 72];    // 18KB
    const int qt = blockIdx.x, h = blockIdx.y, b = blockIdx.z;
    const int tid = threadIdx.x;
    const int lane = tid & 31;
    const int w = tid >> 5;
    const int q4 = lane >> 2;        // group id 0..7
    const int r4 = lane & 3;         // thread-in-group 0..3
    const size_t base = (size_t)b * SEQ * DMODEL + (size_t)h * HD;

    const int row0 = qt * 128 + w * 16 + q4;   // this thread's first q row

    // ---- Q fragments (scale 1/8 folded in; exact pow2) ----
    unsigned qf[8][4];
    {
        const float* Qp = Q + base + (size_t)row0 * DMODEL;
        #pragma unroll
        for (int ks = 0; ks < 8; ks++) {
            qf[ks][0] = __float_as_uint(to_tf32(Qp[ks * 8 + r4] * 0.125f));
            qf[ks][1] = __float_as_uint(to_tf32(Qp[8 * DMODEL + ks * 8 + r4] * 0.125f));
            qf[ks][2] = __float_as_uint(to_tf32(Qp[ks * 8 + r4 + 4] * 0.125f));
            qf[ks][3] = __float_as_uint(to_tf32(Qp[8 * DMODEL + ks * 8 + r4 + 4] * 0.125f));
        }
    }

    float m0 = -1e30f, m1 = -1e30f, l0 = 0.f, l1 = 0.f;
    float oacc[8][4];
    #pragma unroll
    for (int of = 0; of < 8; of++)
        #pragma unroll
        for (int r = 0; r < 4; r++) oacc[of][r] = 0.f;

    const int jmax = 2 * qt + 1;
    for (int j = 0; j <= jmax; j++) {
        __syncthreads();
        // ---- load K (transposed, swizzled) and V tiles ----
        #pragma unroll
        for (int l = 0; l < 4; l++) {
            int f = tid + l * 256;          // 0..1023
            int n = f >> 4;                 // key 0..63
            int dblk = f & 15;              // d/4 block
            float4 kv = *reinterpret_cast<const float4*>(
                K + base + (size_t)(j * 64 + n) * DMODEL + dblk * 4);
            float4 ck;
            ck.x = to_tf32(kv.x); ck.y = to_tf32(kv.y);
            ck.z = to_tf32(kv.z); ck.w = to_tf32(kv.w);
            *reinterpret_cast<float4*>(&Ks[dblk * 256 + ((n ^ (dblk & 7)) << 2)]) = ck;

            float4 vv = *reinterpret_cast<const float4*>(
                V + base + (size_t)(j * 64 + n) * DMODEL + dblk * 4);
            float4 cv;
            cv.x = to_tf32(vv.x); cv.y = to_tf32(vv.y);
            cv.z = to_tf32(vv.z); cv.w = to_tf32(vv.w);
            *reinterpret_cast<float4*>(&Vs[n * 72 + dblk * 4]) = cv;
        }
        __syncthreads();

        // ---- S = (Q/8) K^T : 8 n-frags ----
        float sacc[8][4];
        #pragma unroll
        for (int nf = 0; nf < 8; nf++)
            #pragma unroll
            for (int r = 0; r < 4; r++) sacc[nf][r] = 0.f;

        #pragma unroll
        for (int ks = 0; ks < 8; ks++) {
            const int p0 = (2 * ks) * 256 + ((q4 ^ ((2 * ks) & 7)) << 2) + r4;
            const int p1 = (2 * ks + 1) * 256 + ((q4 ^ ((2 * ks + 1) & 7)) << 2) + r4;
            #pragma unroll
            for (int nf = 0; nf < 8; nf++) {
                unsigned b0 = __float_as_uint(Ks[p0 + nf * 32]);
                unsigned b1 = __float_as_uint(Ks[p1 + nf * 32]);
                asm volatile(
                    "mma.sync.aligned.m16n8k8.row.col.f32.tf32.tf32.f32 "
                    "{%0,%1,%2,%3}, {%4,%5,%6,%7}, {%8,%9}, {%0,%1,%2,%3};"
                    : "+f"(sacc[nf][0]), "+f"(sacc[nf][1]),
                      "+f"(sacc[nf][2]), "+f"(sacc[nf][3])
                    : "r"(qf[ks][0]), "r"(qf[ks][1]), "r"(qf[ks][2]), "r"(qf[ks][3]),
                      "r"(b0), "r"(b1));
            }
        }

        // ---- causal mask (only diagonal tiles) ----
        if (j >= 2 * qt) {
            int gcol0 = j * 64 + r4 * 2;
            #pragma unroll
            for (int nf = 0; nf < 8; nf++) {
                int c = gcol0 + nf * 8;
                if (c     > row0)     sacc[nf][0] = -1e30f;
                if (c + 1 > row0)     sacc[nf][1] = -1e30f;
                if (c     > row0 + 8) sacc[nf][2] = -1e30f;
                if (c + 1 > row0 + 8) sacc[nf][3] = -1e30f;
            }
        }

        // ---- online softmax ----
        float rmax0 = -1e30f, rmax1 = -1e30f;
        #pragma unroll
        for (int nf = 0; nf < 8; nf++) {
            rmax0 = fmaxf(rmax0, fmaxf(sacc[nf][0], sacc[nf][1]));
            rmax1 = fmaxf(rmax1, fmaxf(sacc[nf][2], sacc[nf][3]));
        }
        rmax0 = fmaxf(rmax0, __shfl_xor_sync(0xffffffffu, rmax0, 1));
        rmax0 = fmaxf(rmax0, __shfl_xor_sync(0xffffffffu, rmax0, 2));
        rmax1 = fmaxf(rmax1, __shfl_xor_sync(0xffffffffu, rmax1, 1));
        rmax1 = fmaxf(rmax1, __shfl_xor_sync(0xffffffffu, rmax1, 2));
        float mn0 = fmaxf(m0, rmax0), mn1 = fmaxf(m1, rmax1);
        float al0 = __expf(m0 - mn0), al1 = __expf(m1 - mn1);
        m0 = mn0; m1 = mn1;
        float rs0 = 0.f, rs1 = 0.f;
        #pragma unroll
        for (int nf = 0; nf < 8; nf++) {
            sacc[nf][0] = __expf(sacc[nf][0] - mn0);
            sacc[nf][1] = __expf(sacc[nf][1] - mn0);
            sacc[nf][2] = __expf(sacc[nf][2] - mn1);
            sacc[nf][3] = __expf(sacc[nf][3] - mn1);
            rs0 += sacc[nf][0] + sacc[nf][1];
            rs1 += sacc[nf][2] + sacc[nf][3];
        }
        rs0 += __shfl_xor_sync(0xffffffffu, rs0, 1);
        rs0 += __shfl_xor_sync(0xffffffffu, rs0, 2);
        rs1 += __shfl_xor_sync(0xffffffffu, rs1, 1);
        rs1 += __shfl_xor_sync(0xffffffffu, rs1, 2);
        l0 = l0 * al0 + rs0;
        l1 = l1 * al1 + rs1;
        #pragma unroll
        for (int of = 0; of < 8; of++) {
            oacc[of][0] *= al0; oacc[of][1] *= al0;
            oacc[of][2] *= al1; oacc[of][3] *= al1;
        }

        // ---- O += P @ V (P A-frags built via shfl from sacc) ----
        const int srcA = (lane & 28) | (r4 >> 1);
        const int srcB = srcA | 2;
        const bool odd = (r4 & 1);
        #pragma unroll
        for (int ks = 0; ks < 8; ks++) {
            float v0 = __shfl_sync(0xffffffffu, sacc[ks][0], srcA);
            float v1 = __shfl_sync(0xffffffffu, sacc[ks][1], srcA);
            float v2 = __shfl_sync(0xffffffffu, sacc[ks][2], srcA);
            float v3 = __shfl_sync(0xffffffffu, sacc[ks][3], srcA);
            float u0 = __shfl_sync(0xffffffffu, sacc[ks][0], srcB);
            float u1 = __shfl_sync(0xffffffffu, sacc[ks][1], srcB);
            float u2 = __shfl_sync(0xffffffffu, sacc[ks][2], srcB);
            float u3 = __shfl_sync(0xffffffffu, sacc[ks][3], srcB);
            unsigned a0 = __float_as_uint(to_tf32(odd ? v1 : v0));
            unsigned a1 = __float_as_uint(to_tf32(odd ? v3 : v2));
            unsigned a2 = __float_as_uint(to_tf32(odd ? u1 : u0));
            unsigned a3 = __float_as_uint(to_tf32(odd ? u3 : u2));
            const int vb0 = (ks * 8 + r4) * 72 + q4;
            const int vb1 = (ks * 8 + r4 + 4) * 72 + q4;
            #pragma unroll
            for (int of = 0; of < 8; of++) {
                unsigned b0 = __float_as_uint(Vs[vb0 + of * 8]);
                unsigned b1 = __float_as_uint(Vs[vb1 + of * 8]);
                asm volatile(
                    "mma.sync.aligned.m16n8k8.row.col.f32.tf32.tf32.f32 "
                    "{%0,%1,%2,%3}, {%4,%5,%6,%7}, {%8,%9}, {%0,%1,%2,%3};"
                    : "+f"(oacc[of][0]), "+f"(oacc[of][1]),
                      "+f"(oacc[of][2]), "+f"(oacc[of][3])
                    : "r"(a0), "r"(a1), "r"(a2), "r"(a3),
                      "r"(b0), "r"(b1));
            }
        }
    }

    // ---- epilogue ----
    float inv0 = 1.0f / l0, inv1 = 1.0f / l1;
    #pragma unroll
    for (int of = 0; of < 8; of++) {
        int col = of * 8 + r4 * 2;
        float2 w0 = make_float2(oacc[of][0] * inv0, oacc[of][1] * inv0);
        float2 w1 = make_float2(oacc[of][2] * inv1, oacc[of][3] * inv1);
        *reinterpret_cast<float2*>(&O[base + (size_t)row0 * DMODEL + col]) = w0;
        *reinterpret_cast<float2*>(&O[base + (size_t)(row0 + 8) * DMODEL + col]) = w1;
    }
}

extern "C" void kernel_launch(void* const* d_in, const int* in_sizes, int n_in,
                              void* d_out, int out_size) {
    (void)in_sizes; (void)n_in; (void)out_size;
    const float* x     = (const float*)d_in[0];
    const float* Wq    = (const float*)d_in[1];
    const float* bq    = (const float*)d_in[2];
    const float* Wk    = (const float*)d_in[3];
    const float* bk    = (const float*)d_in[4];
    const float* Wv    = (const float*)d_in[5];
    const float* bv    = (const float*)d_in[6];
    const float* Wo    = (const float*)d_in[7];
    const float* bo    = (const float*)d_in[8];
    const float* gamma = (const float*)d_in[9];
    const float* beta  = (const float*)d_in[10];
    float* out = (float*)d_out;

    float *h, *q, *k, *v, *attn;
    cudaGetSymbolAddress((void**)&h,    g_h);
    cudaGetSymbolAddress((void**)&q,    g_q);
    cudaGetSymbolAddress((void**)&k,    g_k);
    cudaGetSymbolAddress((void**)&v,    g_v);
    cudaGetSymbolAddress((void**)&attn, g_attn);

    ln_kernel<<<MROWS, 256>>>(x, gamma, beta, h);

    dim3 ggrid(DMODEL / 128, MROWS / 128);   // (8, 64)
    gemm_bias_kernel<<<ggrid, 256>>>(h, Wq, bq, q);
    gemm_bias_kernel<<<ggrid, 256>>>(h, Wk, bk, k);
    gemm_bias_kernel<<<ggrid, 256>>>(h, Wv, bv, v);

    attn_tc_kernel<<<dim3(SEQ / 128, NHEAD, BATCH), 256>>>(q, k, v, attn);

    gemm_bias_kernel<<<ggrid, 256>>>(attn, Wo, bo, out);
}

// round 10
// speedup vs baseline: 3.5972x; 1.2198x over previous
#include <cuda_runtime.h>
#include <math.h>

#define DMODEL 1024
#define NHEAD  16
#define HD     64
#define BATCH  4
#define SEQ    2048
#define MROWS  (BATCH*SEQ)   // 8192

#define A_STRIDE 36     // floats; A-frag LDS banks = 4*qid+tg (conflict-free)
#define W_STRIDE 136    // floats; B-frag LDS banks = 8*tg+qid (conflict-free)

// Scratch (allocation-free rule: __device__ globals)
__device__ float g_h[MROWS*DMODEL];
__device__ float g_q[MROWS*DMODEL];
__device__ float g_k[MROWS*DMODEL];
__device__ float g_v[MROWS*DMODEL];
__device__ float g_attn[MROWS*DMODEL];
// tf32-pre-rounded weights
__device__ float g_wq[DMODEL*DMODEL];
__device__ float g_wk[DMODEL*DMODEL];
__device__ float g_wv[DMODEL*DMODEL];
__device__ float g_wo[DMODEL*DMODEL];

__device__ __forceinline__ float to_tf32(float x) {
    float r;
    asm("cvt.rna.tf32.f32 %0, %1;" : "=f"(r) : "f"(x));
    return r;
}

__device__ __forceinline__ unsigned smem_u32(const void* p) {
    return (unsigned)__cvta_generic_to_shared(p);
}
__device__ __forceinline__ void cp_async16(unsigned saddr, const void* gptr) {
    asm volatile("cp.async.cg.shared.global [%0], [%1], 16;\n" :: "r"(saddr), "l"(gptr));
}

// ---------------- tf32 pre-round (weights) ----------------
__global__ void round_tf32_kernel(const float* __restrict__ src, float* __restrict__ dst) {
    int i = blockIdx.x * blockDim.x + threadIdx.x;   // float4 index
    float4 v = reinterpret_cast<const float4*>(src)[i];
    v.x = to_tf32(v.x); v.y = to_tf32(v.y);
    v.z = to_tf32(v.z); v.w = to_tf32(v.w);
    reinterpret_cast<float4*>(dst)[i] = v;
}

// ---------------- LayerNorm: one block per row (tf32-rounded output) ----------------
__global__ void ln_kernel(const float* __restrict__ x,
                          const float* __restrict__ gamma,
                          const float* __restrict__ beta,
                          float* __restrict__ out) {
    int row = blockIdx.x;
    const float* xr = x + (size_t)row * DMODEL;
    float* orow = out + (size_t)row * DMODEL;
    int t = threadIdx.x;                       // 256 threads, 4 floats each
    float4 xv = reinterpret_cast<const float4*>(xr)[t];
    float s  = xv.x + xv.y + xv.z + xv.w;
    float s2 = xv.x*xv.x + xv.y*xv.y + xv.z*xv.z + xv.w*xv.w;
    int lane = t & 31, warp = t >> 5;
    #pragma unroll
    for (int o = 16; o; o >>= 1) {
        s  += __shfl_xor_sync(0xffffffffu, s,  o);
        s2 += __shfl_xor_sync(0xffffffffu, s2, o);
    }
    __shared__ float sh[16];
    if (lane == 0) { sh[warp] = s; sh[8 + warp] = s2; }
    __syncthreads();
    if (t == 0) {
        float a = 0.f, b = 0.f;
        #pragma unroll
        for (int i = 0; i < 8; i++) { a += sh[i]; b += sh[8 + i]; }
        sh[0] = a; sh[1] = b;
    }
    __syncthreads();
    float mean = sh[0] * (1.0f / DMODEL);
    float var  = sh[1] * (1.0f / DMODEL) - mean * mean;
    float rstd = rsqrtf(var + 1e-5f);
    float4 gv = reinterpret_cast<const float4*>(gamma)[t];
    float4 bv = reinterpret_cast<const float4*>(beta)[t];
    float4 ov;
    ov.x = to_tf32((xv.x - mean) * rstd * gv.x + bv.x);
    ov.y = to_tf32((xv.y - mean) * rstd * gv.y + bv.y);
    ov.z = to_tf32((xv.z - mean) * rstd * gv.z + bv.z);
    ov.w = to_tf32((xv.w - mean) * rstd * gv.w + bv.w);
    reinterpret_cast<float4*>(orow)[t] = ov;
}

// ------------- tf32 GEMM 128x128x32, cp.async double-buffered -------------
// C = A@W + bias. Inputs must be tf32-pre-rounded. blockIdx.z selects triple.
__global__ __launch_bounds__(256, 2)
void gemm_bias_kernel(const float* __restrict__ A,
                      const float* __restrict__ W0, const float* __restrict__ bias0, float* __restrict__ C0,
                      const float* __restrict__ W1, const float* __restrict__ bias1, float* __restrict__ C1,
                      const float* __restrict__ W2, const float* __restrict__ bias2, float* __restrict__ C2) {
    const float* W; const float* bias; float* C;
    if (blockIdx.z == 0)      { W = W0; bias = bias0; C = C0; }
    else if (blockIdx.z == 1) { W = W1; bias = bias1; C = C1; }
    else                      { W = W2; bias = bias2; C = C2; }

    __shared__ float As[2][128 * A_STRIDE];   // [m][k] + pad
    __shared__ float Ws[2][32 * W_STRIDE];    // [k][n] + pad

    const int tid = threadIdx.x;
    const int bm = blockIdx.y * 128;
    const int bn = blockIdx.x * 128;
    const int lane = tid & 31;
    const int wid  = tid >> 5;
    const int warp_m = wid & 1;      // 2 warps along M
    const int warp_n = wid >> 1;     // 4 warps along N
    const int qid = lane >> 2;       // 0..7
    const int tg  = lane & 3;        // 0..3

    float acc[4][4][4];
    #pragma unroll
    for (int mi = 0; mi < 4; mi++)
        #pragma unroll
        for (int nj = 0; nj < 4; nj++)
            #pragma unroll
            for (int r = 0; r < 4; r++) acc[mi][nj][r] = 0.f;

    // ---- async tile loader ----
    auto issue_tile = [&](int s, int k0) {
        #pragma unroll
        for (int l = 0; l < 4; l++) {
            int f  = tid + l * 256;          // 0..1023
            int m  = f >> 3;                 // 0..127
            int kc = f & 7;                  // 16B chunk within 32 k
            cp_async16(smem_u32(&As[s][m * A_STRIDE + kc * 4]),
                       A + (size_t)(bm + m) * DMODEL + k0 + kc * 4);
        }
        #pragma unroll
        for (int l = 0; l < 4; l++) {
            int f  = tid + l * 256;
            int k  = f >> 5;                 // 0..31
            int nc = f & 31;
            cp_async16(smem_u32(&Ws[s][k * W_STRIDE + nc * 4]),
                       W + (size_t)(k0 + k) * DMODEL + bn + nc * 4);
        }
        asm volatile("cp.async.commit_group;\n");
    };

    issue_tile(0, 0);

    const int NITER = DMODEL / 32;           // 32
    for (int it = 0; it < NITER; it++) {
        const int s = it & 1;
        if (it + 1 < NITER) {
            issue_tile(s ^ 1, (it + 1) * 32);
            asm volatile("cp.async.wait_group 1;\n");
        } else {
            asm volatile("cp.async.wait_group 0;\n");
        }
        __syncthreads();

        const float* Ab = &As[s][(warp_m * 64 + qid) * A_STRIDE];
        const float* Wb = &Ws[s][warp_n * 32 + qid];
        #pragma unroll
        for (int kk = 0; kk < 4; kk++) {
            const int kA0 = kk * 8 + tg;
            const int kA1 = kA0 + 4;
            unsigned a[4][4], b[4][2];
            #pragma unroll
            for (int mi = 0; mi < 4; mi++) {
                a[mi][0] = __float_as_uint(Ab[(mi * 16 + 0) * A_STRIDE + kA0]);
                a[mi][1] = __float_as_uint(Ab[(mi * 16 + 8) * A_STRIDE + kA0]);
                a[mi][2] = __float_as_uint(Ab[(mi * 16 + 0) * A_STRIDE + kA1]);
                a[mi][3] = __float_as_uint(Ab[(mi * 16 + 8) * A_STRIDE + kA1]);
            }
            #pragma unroll
            for (int nj = 0; nj < 4; nj++) {
                b[nj][0] = __float_as_uint(Wb[kA0 * W_STRIDE + nj * 8]);
                b[nj][1] = __float_as_uint(Wb[kA1 * W_STRIDE + nj * 8]);
            }
            #pragma unroll
            for (int mi = 0; mi < 4; mi++)
                #pragma unroll
                for (int nj = 0; nj < 4; nj++) {
                    asm volatile(
                        "mma.sync.aligned.m16n8k8.row.col.f32.tf32.tf32.f32 "
                        "{%0,%1,%2,%3}, {%4,%5,%6,%7}, {%8,%9}, {%0,%1,%2,%3};"
                        : "+f"(acc[mi][nj][0]), "+f"(acc[mi][nj][1]),
                          "+f"(acc[mi][nj][2]), "+f"(acc[mi][nj][3])
                        : "r"(a[mi][0]), "r"(a[mi][1]), "r"(a[mi][2]), "r"(a[mi][3]),
                          "r"(b[nj][0]), "r"(b[nj][1]));
                }
        }
        __syncthreads();
    }

    #pragma unroll
    for (int mi = 0; mi < 4; mi++) {
        int row = bm + warp_m * 64 + mi * 16 + qid;
        #pragma unroll
        for (int nj = 0; nj < 4; nj++) {
            int col = bn + warp_n * 32 + nj * 8 + tg * 2;
            float b0 = bias[col], b1 = bias[col + 1];
            float2 v0 = make_float2(acc[mi][nj][0] + b0, acc[mi][nj][1] + b1);
            float2 v1 = make_float2(acc[mi][nj][2] + b0, acc[mi][nj][3] + b1);
            *reinterpret_cast<float2*>(&C[(size_t)row * DMODEL + col]) = v0;
            *reinterpret_cast<float2*>(&C[(size_t)(row + 8) * DMODEL + col]) = v1;
        }
    }
}

// ------------- tf32 tensor-core causal flash attention -------------
// CTA: 128 q-rows, 8 warps, each warp owns 16 rows x full 64-key width.
// Epilogue writes tf32-rounded values (consumed by the Wo GEMM).
__global__ __launch_bounds__(256, 1)
void attn_tc_kernel(const float* __restrict__ Q, const float* __restrict__ K,
                    const float* __restrict__ V, float* __restrict__ O) {
    __shared__ float Ks[16 * 256];   // 16KB
    __shared__ float Vs[64 * 72];    // 18KB
    const int qt = blockIdx.x, h = blockIdx.y, b = blockIdx.z;
    const int tid = threadIdx.x;
    const int lane = tid & 31;
    const int w = tid >> 5;
    const int q4 = lane >> 2;        // group id 0..7
    const int r4 = lane & 3;         // thread-in-group 0..3
    const size_t base = (size_t)b * SEQ * DMODEL + (size_t)h * HD;

    const int row0 = qt * 128 + w * 16 + q4;   // this thread's first q row

    // ---- Q fragments (scale 1/8 folded in; exact pow2) ----
    unsigned qf[8][4];
    {
        const float* Qp = Q + base + (size_t)row0 * DMODEL;
        #pragma unroll
        for (int ks = 0; ks < 8; ks++) {
            qf[ks][0] = __float_as_uint(to_tf32(Qp[ks * 8 + r4] * 0.125f));
            qf[ks][1] = __float_as_uint(to_tf32(Qp[8 * DMODEL + ks * 8 + r4] * 0.125f));
            qf[ks][2] = __float_as_uint(to_tf32(Qp[ks * 8 + r4 + 4] * 0.125f));
            qf[ks][3] = __float_as_uint(to_tf32(Qp[8 * DMODEL + ks * 8 + r4 + 4] * 0.125f));
        }
    }

    float m0 = -1e30f, m1 = -1e30f, l0 = 0.f, l1 = 0.f;
    float oacc[8][4];
    #pragma unroll
    for (int of = 0; of < 8; of++)
        #pragma unroll
        for (int r = 0; r < 4; r++) oacc[of][r] = 0.f;

    const int jmax = 2 * qt + 1;
    for (int j = 0; j <= jmax; j++) {
        __syncthreads();
        // ---- load K (transposed, swizzled) and V tiles ----
        #pragma unroll
        for (int l = 0; l < 4; l++) {
            int f = tid + l * 256;          // 0..1023
            int n = f >> 4;                 // key 0..63
            int dblk = f & 15;              // d/4 block
            float4 kv = *reinterpret_cast<const float4*>(
                K + base + (size_t)(j * 64 + n) * DMODEL + dblk * 4);
            float4 ck;
            ck.x = to_tf32(kv.x); ck.y = to_tf32(kv.y);
            ck.z = to_tf32(kv.z); ck.w = to_tf32(kv.w);
            *reinterpret_cast<float4*>(&Ks[dblk * 256 + ((n ^ (dblk & 7)) << 2)]) = ck;

            float4 vv = *reinterpret_cast<const float4*>(
                V + base + (size_t)(j * 64 + n) * DMODEL + dblk * 4);
            float4 cv;
            cv.x = to_tf32(vv.x); cv.y = to_tf32(vv.y);
            cv.z = to_tf32(vv.z); cv.w = to_tf32(vv.w);
            *reinterpret_cast<float4*>(&Vs[n * 72 + dblk * 4]) = cv;
        }
        __syncthreads();

        // ---- S = (Q/8) K^T : 8 n-frags ----
        float sacc[8][4];
        #pragma unroll
        for (int nf = 0; nf < 8; nf++)
            #pragma unroll
            for (int r = 0; r < 4; r++) sacc[nf][r] = 0.f;

        #pragma unroll
        for (int ks = 0; ks < 8; ks++) {
            const int p0 = (2 * ks) * 256 + ((q4 ^ ((2 * ks) & 7)) << 2) + r4;
            const int p1 = (2 * ks + 1) * 256 + ((q4 ^ ((2 * ks + 1) & 7)) << 2) + r4;
            #pragma unroll
            for (int nf = 0; nf < 8; nf++) {
                unsigned b0 = __float_as_uint(Ks[p0 + nf * 32]);
                unsigned b1 = __float_as_uint(Ks[p1 + nf * 32]);
                asm volatile(
                    "mma.sync.aligned.m16n8k8.row.col.f32.tf32.tf32.f32 "
                    "{%0,%1,%2,%3}, {%4,%5,%6,%7}, {%8,%9}, {%0,%1,%2,%3};"
                    : "+f"(sacc[nf][0]), "+f"(sacc[nf][1]),
                      "+f"(sacc[nf][2]), "+f"(sacc[nf][3])
                    : "r"(qf[ks][0]), "r"(qf[ks][1]), "r"(qf[ks][2]), "r"(qf[ks][3]),
                      "r"(b0), "r"(b1));
            }
        }

        // ---- causal mask (only diagonal tiles) ----
        if (j >= 2 * qt) {
            int gcol0 = j * 64 + r4 * 2;
            #pragma unroll
            for (int nf = 0; nf < 8; nf++) {
                int c = gcol0 + nf * 8;
                if (c     > row0)     sacc[nf][0] = -1e30f;
                if (c + 1 > row0)     sacc[nf][1] = -1e30f;
                if (c     > row0 + 8) sacc[nf][2] = -1e30f;
                if (c + 1 > row0 + 8) sacc[nf][3] = -1e30f;
            }
        }

        // ---- online softmax ----
        float rmax0 = -1e30f, rmax1 = -1e30f;
        #pragma unroll
        for (int nf = 0; nf < 8; nf++) {
            rmax0 = fmaxf(rmax0, fmaxf(sacc[nf][0], sacc[nf][1]));
            rmax1 = fmaxf(rmax1, fmaxf(sacc[nf][2], sacc[nf][3]));
        }
        rmax0 = fmaxf(rmax0, __shfl_xor_sync(0xffffffffu, rmax0, 1));
        rmax0 = fmaxf(rmax0, __shfl_xor_sync(0xffffffffu, rmax0, 2));
        rmax1 = fmaxf(rmax1, __shfl_xor_sync(0xffffffffu, rmax1, 1));
        rmax1 = fmaxf(rmax1, __shfl_xor_sync(0xffffffffu, rmax1, 2));
        float mn0 = fmaxf(m0, rmax0), mn1 = fmaxf(m1, rmax1);
        float al0 = __expf(m0 - mn0), al1 = __expf(m1 - mn1);
        m0 = mn0; m1 = mn1;
        float rs0 = 0.f, rs1 = 0.f;
        #pragma unroll
        for (int nf = 0; nf < 8; nf++) {
            sacc[nf][0] = __expf(sacc[nf][0] - mn0);
            sacc[nf][1] = __expf(sacc[nf][1] - mn0);
            sacc[nf][2] = __expf(sacc[nf][2] - mn1);
            sacc[nf][3] = __expf(sacc[nf][3] - mn1);
            rs0 += sacc[nf][0] + sacc[nf][1];
            rs1 += sacc[nf][2] + sacc[nf][3];
        }
        rs0 += __shfl_xor_sync(0xffffffffu, rs0, 1);
        rs0 += __shfl_xor_sync(0xffffffffu, rs0, 2);
        rs1 += __shfl_xor_sync(0xffffffffu, rs1, 1);
        rs1 += __shfl_xor_sync(0xffffffffu, rs1, 2);
        l0 = l0 * al0 + rs0;
        l1 = l1 * al1 + rs1;
        #pragma unroll
        for (int of = 0; of < 8; of++) {
            oacc[of][0] *= al0; oacc[of][1] *= al0;
            oacc[of][2] *= al1; oacc[of][3] *= al1;
        }

        // ---- O += P @ V (P A-frags built via shfl from sacc) ----
        const int srcA = (lane & 28) | (r4 >> 1);
        const int srcB = srcA | 2;
        const bool odd = (r4 & 1);
        #pragma unroll
        for (int ks = 0; ks < 8; ks++) {
            float v0 = __shfl_sync(0xffffffffu, sacc[ks][0], srcA);
            float v1 = __shfl_sync(0xffffffffu, sacc[ks][1], srcA);
            float v2 = __shfl_sync(0xffffffffu, sacc[ks][2], srcA);
            float v3 = __shfl_sync(0xffffffffu, sacc[ks][3], srcA);
            float u0 = __shfl_sync(0xffffffffu, sacc[ks][0], srcB);
            float u1 = __shfl_sync(0xffffffffu, sacc[ks][1], srcB);
            float u2 = __shfl_sync(0xffffffffu, sacc[ks][2], srcB);
            float u3 = __shfl_sync(0xffffffffu, sacc[ks][3], srcB);
            unsigned a0 = __float_as_uint(to_tf32(odd ? v1 : v0));
            unsigned a1 = __float_as_uint(to_tf32(odd ? v3 : v2));
            unsigned a2 = __float_as_uint(to_tf32(odd ? u1 : u0));
            unsigned a3 = __float_as_uint(to_tf32(odd ? u3 : u2));
            const int vb0 = (ks * 8 + r4) * 72 + q4;
            const int vb1 = (ks * 8 + r4 + 4) * 72 + q4;
            #pragma unroll
            for (int of = 0; of < 8; of++) {
                unsigned b0 = __float_as_uint(Vs[vb0 + of * 8]);
                unsigned b1 = __float_as_uint(Vs[vb1 + of * 8]);
                asm volatile(
                    "mma.sync.aligned.m16n8k8.row.col.f32.tf32.tf32.f32 "
                    "{%0,%1,%2,%3}, {%4,%5,%6,%7}, {%8,%9}, {%0,%1,%2,%3};"
                    : "+f"(oacc[of][0]), "+f"(oacc[of][1]),
                      "+f"(oacc[of][2]), "+f"(oacc[of][3])
                    : "r"(a0), "r"(a1), "r"(a2), "r"(a3),
                      "r"(b0), "r"(b1));
            }
        }
    }

    // ---- epilogue (tf32-rounded for the Wo GEMM) ----
    float inv0 = 1.0f / l0, inv1 = 1.0f / l1;
    #pragma unroll
    for (int of = 0; of < 8; of++) {
        int col = of * 8 + r4 * 2;
        float2 w0 = make_float2(to_tf32(oacc[of][0] * inv0), to_tf32(oacc[of][1] * inv0));
        float2 w1 = make_float2(to_tf32(oacc[of][2] * inv1), to_tf32(oacc[of][3] * inv1));
        *reinterpret_cast<float2*>(&O[base + (size_t)row0 * DMODEL + col]) = w0;
        *reinterpret_cast<float2*>(&O[base + (size_t)(row0 + 8) * DMODEL + col]) = w1;
    }
}

extern "C" void kernel_launch(void* const* d_in, const int* in_sizes, int n_in,
                              void* d_out, int out_size) {
    (void)in_sizes; (void)n_in; (void)out_size;
    const float* x     = (const float*)d_in[0];
    const float* Wq    = (const float*)d_in[1];
    const float* bq    = (const float*)d_in[2];
    const float* Wk    = (const float*)d_in[3];
    const float* bk    = (const float*)d_in[4];
    const float* Wv    = (const float*)d_in[5];
    const float* bv    = (const float*)d_in[6];
    const float* Wo    = (const float*)d_in[7];
    const float* bo    = (const float*)d_in[8];
    const float* gamma = (const float*)d_in[9];
    const float* beta  = (const float*)d_in[10];
    float* out = (float*)d_out;

    float *h, *q, *k, *v, *attn, *wq, *wk, *wv, *wo;
    cudaGetSymbolAddress((void**)&h,    g_h);
    cudaGetSymbolAddress((void**)&q,    g_q);
    cudaGetSymbolAddress((void**)&k,    g_k);
    cudaGetSymbolAddress((void**)&v,    g_v);
    cudaGetSymbolAddress((void**)&attn, g_attn);
    cudaGetSymbolAddress((void**)&wq,   g_wq);
    cudaGetSymbolAddress((void**)&wk,   g_wk);
    cudaGetSymbolAddress((void**)&wv,   g_wv);
    cudaGetSymbolAddress((void**)&wo,   g_wo);

    // pre-round weights to tf32 (rna), so GEMMs can cp.async raw bytes
    const int RB = (DMODEL * DMODEL / 4) / 256;   // 1024 blocks
    round_tf32_kernel<<<RB, 256>>>(Wq, wq);
    round_tf32_kernel<<<RB, 256>>>(Wk, wk);
    round_tf32_kernel<<<RB, 256>>>(Wv, wv);
    round_tf32_kernel<<<RB, 256>>>(Wo, wo);

    ln_kernel<<<MROWS, 256>>>(x, gamma, beta, h);

    // fused QKV projection: one launch, z selects (W, bias, C)
    dim3 gqkv(DMODEL / 128, MROWS / 128, 3);   // (8, 64, 3)
    gemm_bias_kernel<<<gqkv, 256>>>(h, wq, bq, q, wk, bk, k, wv, bv, v);

    attn_tc_kernel<<<dim3(SEQ / 128, NHEAD, BATCH), 256>>>(q, k, v, attn);

    dim3 go(DMODEL / 128, MROWS / 128, 1);
    gemm_bias_kernel<<<go, 256>>>(attn, wo, bo, out, wo, bo, out, wo, bo, out);
}